// round 1
// baseline (speedup 1.0000x reference)
#include <cuda_runtime.h>
#include <cuda_bf16.h>
#include <cstdint>

#define N_FEAT 256
#define ROWS_PER_CTA 128
#define XS_STRIDE 260                 // words; chosen so uint2 A-frag loads are 2-phase
#define LSF_WORDS (16 * 1024)         // 16 k-blocks x 8 subtiles x 32 lanes x 4 words
#define SMEM_WORDS (ROWS_PER_CTA * XS_STRIDE + LSF_WORDS)
#define SMEM_BYTES (SMEM_WORDS * 4)

// Precomputed strict-lower W, split into bf16 hi + lo, stored TRANSPOSED [col j][row k]
// so (k, k+1) pairs are contiguous 32-bit words for B-fragment staging.
__device__ __nv_bfloat16 g_LhT[N_FEAT * N_FEAT];
__device__ __nv_bfloat16 g_LlT[N_FEAT * N_FEAT];

// ---------------------------------------------------------------------------
// Kernel 1: build L (strict lower of W), W[i,j] = sum_k v[i, f(j), k] * v[j, f(i), k]
// ---------------------------------------------------------------------------
__global__ void ffm_prep(const float* __restrict__ v, const int* __restrict__ fidx) {
    int i = threadIdx.x;   // row of L (the GEMM k index)
    int j = blockIdx.x;    // col of L
    int fi = fidx[i];
    int fj = fidx[j];
    const float* vi = v + (i * 32 + fj) * 8;
    const float* vj = v + (j * 32 + fi) * 8;
    float s = 0.f;
#pragma unroll
    for (int k = 0; k < 8; ++k) s += vi[k] * vj[k];
    if (i <= j) s = 0.f;                       // strict lower triangle only
    __nv_bfloat16 h = __float2bfloat16(s);
    float lo = s - __bfloat162float(h);
    g_LhT[j * N_FEAT + i] = h;
    g_LlT[j * N_FEAT + i] = __float2bfloat16(lo);
}

// ---------------------------------------------------------------------------
// Kernel 2: out[b] = sum_j x[b,j] * ( w[j] + sum_i x[b,i] * L[i,j] ) + b_lin
// ---------------------------------------------------------------------------
__device__ __forceinline__ void mma_bf16(float c[4], const uint32_t a[4], const uint32_t b[2]) {
    asm volatile(
        "mma.sync.aligned.m16n8k16.row.col.f32.bf16.bf16.f32 "
        "{%0,%1,%2,%3}, {%4,%5,%6,%7}, {%8,%9}, {%0,%1,%2,%3};\n"
        : "+f"(c[0]), "+f"(c[1]), "+f"(c[2]), "+f"(c[3])
        : "r"(a[0]), "r"(a[1]), "r"(a[2]), "r"(a[3]), "r"(b[0]), "r"(b[1]));
}

// word layout: bits[15:0] = bf16 hi part, bits[31:16] = bf16 lo part
__device__ __forceinline__ float upk(uint32_t w) {
    __nv_bfloat162 t = *reinterpret_cast<const __nv_bfloat162*>(&w);
    return __bfloat162float(t.x) + __bfloat162float(t.y);
}

__global__ __launch_bounds__(256, 1) void ffm_main(
    const float* __restrict__ x, const float* __restrict__ wl,
    const float* __restrict__ bl, float* __restrict__ out, int Bn) {
    extern __shared__ uint32_t smem[];
    uint32_t* Xs  = smem;                              // [128][XS_STRIDE] packed hi/lo
    uint32_t* Lsf = smem + ROWS_PER_CTA * XS_STRIDE;   // fragment-ordered L tile

    const int tid  = threadIdx.x;
    const int row0 = blockIdx.x * ROWS_PER_CTA;

    // ---- load X tile, split fp32 -> (bf16 hi, bf16 lo) packed in one word ----
    for (int idx = tid; idx < ROWS_PER_CTA * (N_FEAT / 4); idx += 256) {
        int r  = idx >> 6;
        int c4 = (idx & 63) << 2;
        int gr = row0 + r;
        float4 val;
        if (gr < Bn) val = *reinterpret_cast<const float4*>(x + (size_t)gr * N_FEAT + c4);
        else         val = make_float4(0.f, 0.f, 0.f, 0.f);
        float vv[4] = {val.x, val.y, val.z, val.w};
#pragma unroll
        for (int q = 0; q < 4; ++q) {
            __nv_bfloat16 h = __float2bfloat16(vv[q]);
            float lof = vv[q] - __bfloat162float(h);
            __nv_bfloat16 l = __float2bfloat16(lof);
            Xs[r * XS_STRIDE + c4 + q] =
                (uint32_t)__bfloat16_as_ushort(h) | ((uint32_t)__bfloat16_as_ushort(l) << 16);
        }
    }
    __syncthreads();

    const int warp = tid >> 5, lane = tid & 31;
    const int g = lane >> 2, tg = lane & 3;
    const int rb  = warp * 16;
    const int r0o = (rb + g) * XS_STRIDE;
    const int r1o = (rb + g + 8) * XS_STRIDE;

    float partial0 = 0.f, partial1 = 0.f;

    for (int jt = 0; jt < 4; ++jt) {
        const int jtbase = jt * 64;
        const int kb0    = jt * 4;   // k-blocks below the diagonal block are all-zero: skip

        // ---- stage L[k >= jtbase, jtbase:jtbase+64] in per-warp fragment order ----
        // layout: [kb][sub(8)][lane(32)][4 words: b01_hi, b23_hi, b01_lo, b23_lo]
        const int nwords = (16 - kb0) * 1024;
        for (int idx = tid; idx < nwords; idx += 256) {
            int kb = kb0 + (idx >> 10);
            int r  = idx & 1023;
            int sub = r >> 7;
            int ln  = (r >> 2) & 31;
            int w   = r & 3;
            int gg  = ln >> 2, tt = ln & 3;
            int j   = jtbase + sub * 8 + gg;
            const uint32_t* src32 =
                reinterpret_cast<const uint32_t*>((w & 2) ? g_LlT : g_LhT);
            int kw = kb * 8 + ((w & 1) ? 4 : 0) + tt;
            Lsf[kb * 1024 + r] = src32[j * (N_FEAT / 2) + kw];
        }
        __syncthreads();

        // ---- accumulators init with w_lin (adds x·w exactly once overall) ----
        float acc[8][4];
#pragma unroll
        for (int sub = 0; sub < 8; ++sub) {
            int j0 = jtbase + sub * 8 + tg * 2;
            float w0 = wl[j0], w1 = wl[j0 + 1];
            acc[sub][0] = w0; acc[sub][1] = w1; acc[sub][2] = w0; acc[sub][3] = w1;
        }

        // ---- k loop: Z(:, jt-tile) += X(:, k-tile) * L(k-tile, jt-tile) (3-term split)
        for (int kb = kb0; kb < 16; ++kb) {
            int k0 = kb * 16 + tg * 2;
            uint2 x0a = *reinterpret_cast<const uint2*>(&Xs[r0o + k0]);
            uint2 x1a = *reinterpret_cast<const uint2*>(&Xs[r1o + k0]);
            uint2 x0b = *reinterpret_cast<const uint2*>(&Xs[r0o + k0 + 8]);
            uint2 x1b = *reinterpret_cast<const uint2*>(&Xs[r1o + k0 + 8]);
            uint32_t ah[4], al[4];
            ah[0] = __byte_perm(x0a.x, x0a.y, 0x5410); al[0] = __byte_perm(x0a.x, x0a.y, 0x7632);
            ah[1] = __byte_perm(x1a.x, x1a.y, 0x5410); al[1] = __byte_perm(x1a.x, x1a.y, 0x7632);
            ah[2] = __byte_perm(x0b.x, x0b.y, 0x5410); al[2] = __byte_perm(x0b.x, x0b.y, 0x7632);
            ah[3] = __byte_perm(x1b.x, x1b.y, 0x5410); al[3] = __byte_perm(x1b.x, x1b.y, 0x7632);
#pragma unroll
            for (int sub = 0; sub < 8; ++sub) {
                uint4 bb = *reinterpret_cast<const uint4*>(&Lsf[kb * 1024 + sub * 128 + lane * 4]);
                uint32_t bh[2]  = {bb.x, bb.y};
                uint32_t blo[2] = {bb.z, bb.w};
                mma_bf16(acc[sub], ah, bh);    // xh * Lh
                mma_bf16(acc[sub], ah, blo);   // xh * Ll
                mma_bf16(acc[sub], al, bh);    // xl * Lh
            }
        }

        // ---- fused epilogue: partial += x .* (Z + w) over this column tile ----
#pragma unroll
        for (int sub = 0; sub < 8; ++sub) {
            int j0 = jtbase + sub * 8 + tg * 2;
            partial0 += acc[sub][0] * upk(Xs[r0o + j0]) + acc[sub][1] * upk(Xs[r0o + j0 + 1]);
            partial1 += acc[sub][2] * upk(Xs[r1o + j0]) + acc[sub][3] * upk(Xs[r1o + j0 + 1]);
        }
        __syncthreads();  // protect Lsf before next jt overwrites it
    }

    // reduce across the 4 threads (tg) that share each row
    partial0 += __shfl_xor_sync(0xffffffffu, partial0, 1);
    partial0 += __shfl_xor_sync(0xffffffffu, partial0, 2);
    partial1 += __shfl_xor_sync(0xffffffffu, partial1, 1);
    partial1 += __shfl_xor_sync(0xffffffffu, partial1, 2);

    if (tg == 0) {
        float bv = bl[0];
        int gr0 = row0 + rb + g;
        if (gr0 < Bn) out[gr0] = partial0 + bv;
        int gr1 = gr0 + 8;
        if (gr1 < Bn) out[gr1] = partial1 + bv;
    }
}

// ---------------------------------------------------------------------------
extern "C" void kernel_launch(void* const* d_in, const int* in_sizes, int n_in,
                              void* d_out, int out_size) {
    const float* x    = (const float*)d_in[0];
    const float* wlin = (const float*)d_in[1];
    const float* blin = (const float*)d_in[2];
    const float* v    = (const float*)d_in[3];
    const int*   fidx = (const int*)d_in[4];
    float* out = (float*)d_out;

    int Bn = in_sizes[0] / N_FEAT;

    ffm_prep<<<N_FEAT, N_FEAT>>>(v, fidx);

    cudaFuncSetAttribute(ffm_main, cudaFuncAttributeMaxDynamicSharedMemorySize, SMEM_BYTES);
    int grid = (Bn + ROWS_PER_CTA - 1) / ROWS_PER_CTA;
    ffm_main<<<grid, 256, SMEM_BYTES>>>(x, wlin, blin, out, Bn);
}

// round 2
// speedup vs baseline: 1.0305x; 1.0305x over previous
#include <cuda_runtime.h>
#include <cuda_bf16.h>
#include <cstdint>

#define N_FEAT 256
#define ROWS_PER_CTA 128
#define XS_STRIDE 260                 // words; chosen so uint2 A-frag loads are 2-phase
#define LSF_WORDS (16 * 1024)         // 16 k-blocks x 8 subtiles x 32 lanes x 4 words
#define SMEM_WORDS (ROWS_PER_CTA * XS_STRIDE + LSF_WORDS + ROWS_PER_CTA)
#define SMEM_BYTES (SMEM_WORDS * 4)

// Precomputed strict-lower W, split into bf16 hi + lo, stored TRANSPOSED [col j][row k]
// so (k, k+1) pairs are contiguous 32-bit words for B-fragment staging.
__device__ __nv_bfloat16 g_LhT[N_FEAT * N_FEAT];
__device__ __nv_bfloat16 g_LlT[N_FEAT * N_FEAT];

// ---------------------------------------------------------------------------
// Kernel 1: build L (strict lower of W), W[i,j] = sum_k v[i, f(j), k] * v[j, f(i), k]
// ---------------------------------------------------------------------------
__global__ void ffm_prep(const float* __restrict__ v, const int* __restrict__ fidx) {
    int i = threadIdx.x;   // row of L (the GEMM k index)
    int j = blockIdx.x;    // col of L
    int fi = fidx[i];
    int fj = fidx[j];
    const float* vi = v + (i * 32 + fj) * 8;
    const float* vj = v + (j * 32 + fi) * 8;
    float s = 0.f;
#pragma unroll
    for (int k = 0; k < 8; ++k) s += vi[k] * vj[k];
    if (i <= j) s = 0.f;                       // strict lower triangle only
    __nv_bfloat16 h = __float2bfloat16(s);
    float lo = s - __bfloat162float(h);
    g_LhT[j * N_FEAT + i] = h;
    g_LlT[j * N_FEAT + i] = __float2bfloat16(lo);
}

// ---------------------------------------------------------------------------
// Kernel 2: out[b] = sum_j x[b,j] * ( w[j] + sum_i x[b,i] * L[i,j] ) + b_lin
// 512 threads: 16 warps; warp = (rowgroup rg in 0..7) x (jhalf in 0..1).
// Each warp does a 16-row x 32-col slice of Z, full k range.
// ---------------------------------------------------------------------------
__device__ __forceinline__ void mma_bf16(float c[4], const uint32_t a[4], const uint32_t b[2]) {
    asm volatile(
        "mma.sync.aligned.m16n8k16.row.col.f32.bf16.bf16.f32 "
        "{%0,%1,%2,%3}, {%4,%5,%6,%7}, {%8,%9}, {%0,%1,%2,%3};\n"
        : "+f"(c[0]), "+f"(c[1]), "+f"(c[2]), "+f"(c[3])
        : "r"(a[0]), "r"(a[1]), "r"(a[2]), "r"(a[3]), "r"(b[0]), "r"(b[1]));
}

// word layout: bits[15:0] = bf16 hi part, bits[31:16] = bf16 lo part
__device__ __forceinline__ float upk(uint32_t w) {
    __nv_bfloat162 t = *reinterpret_cast<const __nv_bfloat162*>(&w);
    return __bfloat162float(t.x) + __bfloat162float(t.y);
}

__global__ __launch_bounds__(512, 1) void ffm_main(
    const float* __restrict__ x, const float* __restrict__ wl,
    const float* __restrict__ bl, float* __restrict__ out, int Bn) {
    extern __shared__ uint32_t smem[];
    uint32_t* Xs  = smem;                              // [128][XS_STRIDE] packed hi/lo
    uint32_t* Lsf = smem + ROWS_PER_CTA * XS_STRIDE;   // fragment-ordered L tile
    float* rowsum = reinterpret_cast<float*>(Lsf + LSF_WORDS);  // [128]

    const int tid  = threadIdx.x;
    const int row0 = blockIdx.x * ROWS_PER_CTA;

    if (tid < ROWS_PER_CTA) rowsum[tid] = 0.f;

    // ---- load X tile, split fp32 -> (bf16 hi, bf16 lo) packed in one word ----
    for (int idx = tid; idx < ROWS_PER_CTA * (N_FEAT / 4); idx += 512) {
        int r  = idx >> 6;
        int c4 = (idx & 63) << 2;
        int gr = row0 + r;
        float4 val;
        if (gr < Bn) val = *reinterpret_cast<const float4*>(x + (size_t)gr * N_FEAT + c4);
        else         val = make_float4(0.f, 0.f, 0.f, 0.f);
        float vv[4] = {val.x, val.y, val.z, val.w};
#pragma unroll
        for (int q = 0; q < 4; ++q) {
            __nv_bfloat16 h = __float2bfloat16(vv[q]);
            float lof = vv[q] - __bfloat162float(h);
            __nv_bfloat16 l = __float2bfloat16(lof);
            Xs[r * XS_STRIDE + c4 + q] =
                (uint32_t)__bfloat16_as_ushort(h) | ((uint32_t)__bfloat16_as_ushort(l) << 16);
        }
    }
    __syncthreads();

    const int warp = tid >> 5, lane = tid & 31;
    const int rg    = warp >> 1;        // 0..7, 16 rows each
    const int jhalf = warp & 1;         // 0..1, 4 subtiles each
    const int g = lane >> 2, tg = lane & 3;
    const int rb  = rg * 16;
    const int r0o = (rb + g) * XS_STRIDE;
    const int r1o = (rb + g + 8) * XS_STRIDE;

    float partial0 = 0.f, partial1 = 0.f;

    for (int jt = 0; jt < 4; ++jt) {
        const int jtbase = jt * 64;
        const int kb0    = jt * 4;   // k-blocks below the diagonal block are all-zero: skip

        // ---- stage L[k >= jtbase, jtbase:jtbase+64] in per-warp fragment order ----
        // layout: [kb][sub(8)][lane(32)][4 words: b01_hi, b23_hi, b01_lo, b23_lo]
        const int nwords = (16 - kb0) * 1024;
        for (int idx = tid; idx < nwords; idx += 512) {
            int kb = kb0 + (idx >> 10);
            int r  = idx & 1023;
            int sub = r >> 7;
            int ln  = (r >> 2) & 31;
            int w   = r & 3;
            int gg  = ln >> 2, tt = ln & 3;
            int j   = jtbase + sub * 8 + gg;
            const uint32_t* src32 =
                reinterpret_cast<const uint32_t*>((w & 2) ? g_LlT : g_LhT);
            int kw = kb * 8 + ((w & 1) ? 4 : 0) + tt;
            Lsf[kb * 1024 + r] = src32[j * (N_FEAT / 2) + kw];
        }
        __syncthreads();

        // ---- accumulators init with w_lin (adds x·w exactly once overall) ----
        float acc[4][4];
#pragma unroll
        for (int s = 0; s < 4; ++s) {
            int sub = jhalf * 4 + s;
            int j0 = jtbase + sub * 8 + tg * 2;
            float w0 = wl[j0], w1 = wl[j0 + 1];
            acc[s][0] = w0; acc[s][1] = w1; acc[s][2] = w0; acc[s][3] = w1;
        }

        // ---- k loop: Z(:, jt-tile) += X(:, k-tile) * L(k-tile, jt-tile) (3-term split)
        for (int kb = kb0; kb < 16; ++kb) {
            int k0 = kb * 16 + tg * 2;
            uint2 x0a = *reinterpret_cast<const uint2*>(&Xs[r0o + k0]);
            uint2 x1a = *reinterpret_cast<const uint2*>(&Xs[r1o + k0]);
            uint2 x0b = *reinterpret_cast<const uint2*>(&Xs[r0o + k0 + 8]);
            uint2 x1b = *reinterpret_cast<const uint2*>(&Xs[r1o + k0 + 8]);
            uint32_t ah[4], al[4];
            ah[0] = __byte_perm(x0a.x, x0a.y, 0x5410); al[0] = __byte_perm(x0a.x, x0a.y, 0x7632);
            ah[1] = __byte_perm(x1a.x, x1a.y, 0x5410); al[1] = __byte_perm(x1a.x, x1a.y, 0x7632);
            ah[2] = __byte_perm(x0b.x, x0b.y, 0x5410); al[2] = __byte_perm(x0b.x, x0b.y, 0x7632);
            ah[3] = __byte_perm(x1b.x, x1b.y, 0x5410); al[3] = __byte_perm(x1b.x, x1b.y, 0x7632);
#pragma unroll
            for (int s = 0; s < 4; ++s) {
                int sub = jhalf * 4 + s;
                uint4 bb = *reinterpret_cast<const uint4*>(&Lsf[kb * 1024 + sub * 128 + lane * 4]);
                uint32_t bh[2]  = {bb.x, bb.y};
                uint32_t blo[2] = {bb.z, bb.w};
                mma_bf16(acc[s], ah, bh);    // xh * Lh
                mma_bf16(acc[s], ah, blo);   // xh * Ll
                mma_bf16(acc[s], al, bh);    // xl * Lh
            }
        }

        // ---- fused epilogue: partial += x .* (Z + w) over this warp's 32 cols ----
#pragma unroll
        for (int s = 0; s < 4; ++s) {
            int sub = jhalf * 4 + s;
            int j0 = jtbase + sub * 8 + tg * 2;
            partial0 += acc[s][0] * upk(Xs[r0o + j0]) + acc[s][1] * upk(Xs[r0o + j0 + 1]);
            partial1 += acc[s][2] * upk(Xs[r1o + j0]) + acc[s][3] * upk(Xs[r1o + j0 + 1]);
        }
        __syncthreads();  // protect Lsf before next jt overwrites it
    }

    // reduce across the 4 threads (tg) that share each row
    partial0 += __shfl_xor_sync(0xffffffffu, partial0, 1);
    partial0 += __shfl_xor_sync(0xffffffffu, partial0, 2);
    partial1 += __shfl_xor_sync(0xffffffffu, partial1, 1);
    partial1 += __shfl_xor_sync(0xffffffffu, partial1, 2);

    // combine the two j-halves (warp pairs) via smem atomics
    if (tg == 0) {
        atomicAdd(&rowsum[rb + g],     partial0);
        atomicAdd(&rowsum[rb + g + 8], partial1);
    }
    __syncthreads();

    if (tid < ROWS_PER_CTA) {
        int gr = row0 + tid;
        if (gr < Bn) out[gr] = rowsum[tid] + bl[0];
    }
}

// ---------------------------------------------------------------------------
extern "C" void kernel_launch(void* const* d_in, const int* in_sizes, int n_in,
                              void* d_out, int out_size) {
    const float* x    = (const float*)d_in[0];
    const float* wlin = (const float*)d_in[1];
    const float* blin = (const float*)d_in[2];
    const float* v    = (const float*)d_in[3];
    const int*   fidx = (const int*)d_in[4];
    float* out = (float*)d_out;

    int Bn = in_sizes[0] / N_FEAT;

    ffm_prep<<<N_FEAT, N_FEAT>>>(v, fidx);

    cudaFuncSetAttribute(ffm_main, cudaFuncAttributeMaxDynamicSharedMemorySize, SMEM_BYTES);
    int grid = (Bn + ROWS_PER_CTA - 1) / ROWS_PER_CTA;
    ffm_main<<<grid, 512, SMEM_BYTES>>>(x, wlin, blin, out, Bn);
}

// round 7
// speedup vs baseline: 2.6122x; 2.5348x over previous
#include <cuda_runtime.h>
#include <cuda_fp16.h>
#include <cstdint>

#define N_FEAT 256
#define ROWS 128                       // M rows per CTA

// B in fragment order, global: [jt(4)][kb(16)][sub(8)][lane(32)] -> uint2
// word0 = half2( L[k0][j], L[k0+1][j] ),  word1 = half2( L[k0+8][j], L[k0+9][j] )
// with j = jt*64 + sub*8 + (lane>>2), k0 = kb*16 + (lane&3)*2
// L[k][j] = W[k][j] if k > j else 0  (strict lower; validated in R1)
__device__ __align__(16) uint2 g_Bf[4 * 16 * 8 * 32];

// ---- smem layout (bytes) ----
#define OFF_AFRAG 0                    // 8 rg x 16 kb x 32 lanes x uint4 = 64KB
#define OFF_WL    65536                // 256 floats
#define OFF_RS    66560                // 128 floats rowsum
#define SMEM_TOTAL 67072

// ---------------------------------------------------------------------------
// Prep: compute W fragments directly.  W[k][j] = sum_m v[k,f(j),m] * v[j,f(k),m]
// ---------------------------------------------------------------------------
__global__ void ffm_prep(const float* __restrict__ v, const int* __restrict__ fidx) {
    int idx = blockIdx.x * blockDim.x + threadIdx.x;   // 0 .. 16383
    if (idx >= 4 * 16 * 8 * 32) return;
    int lane = idx & 31;
    int sub  = (idx >> 5) & 7;
    int kb   = (idx >> 8) & 15;
    int jt   = idx >> 12;
    int g  = lane >> 2, tg = lane & 3;
    int j  = jt * 64 + sub * 8 + g;
    int k0 = kb * 16 + tg * 2;
    int fj = fidx[j];
    const float* vjr = v + (j * 32) * 8;   // v[j, :, :]

    float lv[4];
    int kk[4] = {k0, k0 + 1, k0 + 8, k0 + 9};
#pragma unroll
    for (int q = 0; q < 4; ++q) {
        int k = kk[q];
        float s = 0.f;
        if (k > j) {
            int fk = fidx[k];
            const float* a = v + (k * 32 + fj) * 8;
            const float* b = vjr + fk * 8;
#pragma unroll
            for (int m = 0; m < 8; ++m) s += a[m] * b[m];
        }
        lv[q] = s;
    }
    __half2 w0 = __floats2half2_rn(lv[0], lv[1]);
    __half2 w1 = __floats2half2_rn(lv[2], lv[3]);
    uint2 o;
    o.x = *reinterpret_cast<uint32_t*>(&w0);
    o.y = *reinterpret_cast<uint32_t*>(&w1);
    g_Bf[idx] = o;
}

// ---------------------------------------------------------------------------
__device__ __forceinline__ void mma_f16(float c[4], const uint32_t a[4], const uint32_t b[2]) {
    asm volatile(
        "mma.sync.aligned.m16n8k16.row.col.f32.f16.f16.f32 "
        "{%0,%1,%2,%3}, {%4,%5,%6,%7}, {%8,%9}, {%0,%1,%2,%3};\n"
        : "+f"(c[0]), "+f"(c[1]), "+f"(c[2]), "+f"(c[3])
        : "r"(a[0]), "r"(a[1]), "r"(a[2]), "r"(a[3]), "r"(b[0]), "r"(b[1]));
}

// Main: Z = X * L (fp16 single-term, triangular-skipped), fused epilogue
//       out[b] = sum_j x[b,j] * (w[j] + Z[b,j]) + b_lin
// 512 threads = 16 warps: warp = rg(0..7) x jhalf(0..1). 2 CTAs/SM.
__global__ __launch_bounds__(512, 2) void ffm_main(
    const float* __restrict__ x, const float* __restrict__ wl,
    const float* __restrict__ bl, float* __restrict__ out, int Bn) {
    extern __shared__ char smem[];
    uint4*  afrag  = reinterpret_cast<uint4*>(smem + OFF_AFRAG);
    float*  wls    = reinterpret_cast<float*>(smem + OFF_WL);
    float*  rowsum = reinterpret_cast<float*>(smem + OFF_RS);

    const int tid  = threadIdx.x;
    const int row0 = blockIdx.x * ROWS;

    if (tid < 256) wls[tid] = wl[tid];
    if (tid < 128) rowsum[tid] = 0.f;

    // ---- stage A fragments: x fp32 -> fp16, mma a-fragment order ----
    // afrag[(rg*16+kb)*32 + lane] = {h2(r0,klo), h2(r1,klo), h2(r0,khi), h2(r1,khi)}
    for (int it = tid; it < 4096; it += 512) {
        int ln = it & 31;
        int kb = (it >> 5) & 15;
        int rg = it >> 9;
        int g = ln >> 2, tg = ln & 3;
        int r0 = rg * 16 + g, r1 = r0 + 8;
        int c0 = kb * 16 + tg * 2;
        int gr0 = row0 + r0, gr1 = row0 + r1;
        float2 z2 = make_float2(0.f, 0.f);
        float2 v00 = (gr0 < Bn) ? *reinterpret_cast<const float2*>(x + (size_t)gr0 * N_FEAT + c0)     : z2;
        float2 v01 = (gr0 < Bn) ? *reinterpret_cast<const float2*>(x + (size_t)gr0 * N_FEAT + c0 + 8) : z2;
        float2 v10 = (gr1 < Bn) ? *reinterpret_cast<const float2*>(x + (size_t)gr1 * N_FEAT + c0)     : z2;
        float2 v11 = (gr1 < Bn) ? *reinterpret_cast<const float2*>(x + (size_t)gr1 * N_FEAT + c0 + 8) : z2;
        __half2 h00 = __floats2half2_rn(v00.x, v00.y);
        __half2 h10 = __floats2half2_rn(v10.x, v10.y);
        __half2 h01 = __floats2half2_rn(v01.x, v01.y);
        __half2 h11 = __floats2half2_rn(v11.x, v11.y);
        uint4 o;
        o.x = *reinterpret_cast<uint32_t*>(&h00);
        o.y = *reinterpret_cast<uint32_t*>(&h10);
        o.z = *reinterpret_cast<uint32_t*>(&h01);
        o.w = *reinterpret_cast<uint32_t*>(&h11);
        afrag[(rg * 16 + kb) * 32 + ln] = o;
    }
    __syncthreads();     // only sync before output; B comes from global, acc in regs

    const int wid = tid >> 5, lane = tid & 31;
    const int rg = wid >> 1, jhalf = wid & 1;
    const int g = lane >> 2, tg = lane & 3;

    float partial0 = 0.f, partial1 = 0.f;

    for (int jt = 0; jt < 4; ++jt) {
        const int kb0 = jt * 4;

        float acc[4][4];
#pragma unroll
        for (int s = 0; s < 4; ++s)
#pragma unroll
            for (int q = 0; q < 4; ++q) acc[s][q] = 0.f;

        const uint4* ap = &afrag[(rg * 16 + kb0) * 32 + lane];
        const uint2* bp = &g_Bf[((jt * 16 + kb0) * 8 + jhalf * 4) * 32 + lane];

        // prefetch first
        uint4 a_cur = *ap;
        uint2 b_cur[4];
#pragma unroll
        for (int s = 0; s < 4; ++s) b_cur[s] = bp[s * 32];

        for (int kb = kb0; kb < 16; ++kb) {
            uint4 a_nxt;
            uint2 b_nxt[4];
            if (kb + 1 < 16) {
                a_nxt = ap[32];
#pragma unroll
                for (int s = 0; s < 4; ++s) b_nxt[s] = bp[256 + s * 32];
            }
            uint32_t a[4] = {a_cur.x, a_cur.y, a_cur.z, a_cur.w};
#pragma unroll
            for (int s = 0; s < 4; ++s) {
                uint32_t b[2] = {b_cur[s].x, b_cur[s].y};
                mma_f16(acc[s], a, b);
            }
            a_cur = a_nxt;
#pragma unroll
            for (int s = 0; s < 4; ++s) b_cur[s] = b_nxt[s];
            ap += 32;
            bp += 256;
        }

        // ---- fused epilogue: partial += (Z + w) .* x over this warp's 32 cols ----
        // C frag: c0,c1 = row g cols 2tg,2tg+1; c2,c3 = row g+8 same cols (per 8-col sub)
        // x values = A-frag at kb' = jt*4 + jhalf*2 + spair (even local sub: .x/.y words,
        // odd local sub: .z/.w words).  NOTE: acc[] is indexed by LOCAL sub sl (0..3);
        // the global sub se is used only to form the column index jbase.
#pragma unroll
        for (int spair = 0; spair < 2; ++spair) {
            int kbp = jt * 4 + jhalf * 2 + spair;
            uint4 av = afrag[(rg * 16 + kbp) * 32 + lane];
            int sl = spair * 2;                   // local acc index (even sub of the pair)
            int se = jhalf * 4 + sl;              // global sub (for column numbering)
            int jbase = jt * 64 + se * 8 + tg * 2;
            float we0 = wls[jbase],     we1 = wls[jbase + 1];
            float wo0 = wls[jbase + 8], wo1 = wls[jbase + 9];
            float2 xe0 = __half22float2(*reinterpret_cast<__half2*>(&av.x));  // row g, even sub
            float2 xe1 = __half22float2(*reinterpret_cast<__half2*>(&av.y));  // row g+8
            float2 xo0 = __half22float2(*reinterpret_cast<__half2*>(&av.z));  // row g, odd sub
            float2 xo1 = __half22float2(*reinterpret_cast<__half2*>(&av.w));  // row g+8
            partial0 += (acc[sl][0] + we0) * xe0.x + (acc[sl][1] + we1) * xe0.y;
            partial1 += (acc[sl][2] + we0) * xe1.x + (acc[sl][3] + we1) * xe1.y;
            partial0 += (acc[sl + 1][0] + wo0) * xo0.x + (acc[sl + 1][1] + wo1) * xo0.y;
            partial1 += (acc[sl + 1][2] + wo0) * xo1.x + (acc[sl + 1][3] + wo1) * xo1.y;
        }
    }

    // reduce over the 4 lanes (tg) sharing each row
    partial0 += __shfl_xor_sync(0xffffffffu, partial0, 1);
    partial0 += __shfl_xor_sync(0xffffffffu, partial0, 2);
    partial1 += __shfl_xor_sync(0xffffffffu, partial1, 1);
    partial1 += __shfl_xor_sync(0xffffffffu, partial1, 2);

    if (tg == 0) {
        atomicAdd(&rowsum[rg * 16 + g],     partial0);
        atomicAdd(&rowsum[rg * 16 + g + 8], partial1);
    }
    __syncthreads();

    if (tid < 128) {
        int gr = row0 + tid;
        if (gr < Bn) out[gr] = rowsum[tid] + bl[0];
    }
}

// ---------------------------------------------------------------------------
extern "C" void kernel_launch(void* const* d_in, const int* in_sizes, int n_in,
                              void* d_out, int out_size) {
    const float* x    = (const float*)d_in[0];
    const float* wlin = (const float*)d_in[1];
    const float* blin = (const float*)d_in[2];
    const float* v    = (const float*)d_in[3];
    const int*   fidx = (const int*)d_in[4];
    float* out = (float*)d_out;

    int Bn = in_sizes[0] / N_FEAT;

    ffm_prep<<<32, 512>>>(v, fidx);

    cudaFuncSetAttribute(ffm_main, cudaFuncAttributeMaxDynamicSharedMemorySize, SMEM_TOTAL);
    int grid = (Bn + ROWS - 1) / ROWS;
    ffm_main<<<grid, 512, SMEM_TOTAL>>>(x, wlin, blin, out, Bn);
}